// round 14
// baseline (speedup 1.0000x reference)
#include <cuda_runtime.h>
#include <cuda_fp16.h>

typedef unsigned int u32;
typedef unsigned long long u64;

// ---------------- problem constants ----------------
static constexpr int M = 4096;     // batch
static constexpr int N = 11008;    // out features
static constexpr int K = 4096;     // in features
static constexpr int NGROUPS = 32; // K / 128
static constexpr float ALPHA_C = 0.05f;

// ---------------- GEMM tiling (baseline-PTX Ampere-style) ----------------
static constexpr int BM = 128;
static constexpr int BN = 128;
static constexpr int BK = 64;                // halves per chunk (128B rows, SW128)
static constexpr int STAGES = 3;
static constexpr int NCHUNK = K / BK;        // 64
static constexpr int NTHREADS = 256;         // 8 warps, each 32x64

static constexpr int A_BYTES = BM * BK * 2;  // 16384
static constexpr int B_BYTES = BN * BK * 2;  // 16384
static constexpr int OFF_A = 0;
static constexpr int OFF_B = STAGES * A_BYTES;               // 49152
static constexpr int SMEM_TOTAL = OFF_B + STAGES * B_BYTES;  // 98304 (96KB, 2 CTAs/SM)

static constexpr int MBLKS = M / BM;         // 32
static constexpr int NBLKS = N / BN;         // 86
static constexpr int RASTER_G = 8;           // n-blocks per raster group

// ---------------- scratch (no cudaMalloc allowed) ----------------
__device__ __half g_W[(size_t)N * K];   // dequantized noisy weights, fp16, [N,K] row-major
__device__ __half g_X[(size_t)M * K];   // x in fp16, [M,K] row-major

// ---------------- helpers ----------------
__device__ __forceinline__ u32 smem_u32(const void* p) {
    u32 a;
    asm("{ .reg .u64 t; cvta.to.shared.u64 t, %1; cvt.u32.u64 %0, t; }" : "=r"(a) : "l"(p));
    return a;
}
__device__ __forceinline__ void cp16(u32 dst, const void* src) {
    asm volatile("cp.async.cg.shared.global [%0], [%1], 16;" :: "r"(dst), "l"(src));
}
__device__ __forceinline__ void cp_commit() { asm volatile("cp.async.commit_group;"); }
template <int NN> __device__ __forceinline__ void cp_wait() {
    asm volatile("cp.async.wait_group %0;" :: "n"(NN));
}
__device__ __forceinline__ void ldsm_x4(u32& r0, u32& r1, u32& r2, u32& r3, u32 addr) {
    asm volatile("ldmatrix.sync.aligned.m8n8.x4.shared.b16 {%0,%1,%2,%3}, [%4];"
                 : "=r"(r0), "=r"(r1), "=r"(r2), "=r"(r3) : "r"(addr));
}
__device__ __forceinline__ void mma16816(float* d, const u32* a, u32 b0, u32 b1) {
    asm volatile(
        "mma.sync.aligned.m16n8k16.row.col.f32.f16.f16.f32 "
        "{%0,%1,%2,%3}, {%4,%5,%6,%7}, {%8,%9}, {%0,%1,%2,%3};"
        : "+f"(d[0]), "+f"(d[1]), "+f"(d[2]), "+f"(d[3])
        : "r"(a[0]), "r"(a[1]), "r"(a[2]), "r"(a[3]), "r"(b0), "r"(b1));
}

// SW128 swizzle for 128B rows: bits[6:4] ^= bits[9:7]
#define SWZ128(o) ((u32)(o) ^ ((((u32)(o)) >> 3) & 0x70))

// ---------------- prep kernels ----------------
// W_noisy[o,k] = fp16( w + 0.05*noise*|w| ),  w = (q - zero[o,g]) * scale[o,g]
__global__ void dequant_noise_kernel(const int* __restrict__ q,
                                     const float* __restrict__ sc,
                                     const float* __restrict__ zr,
                                     const float* __restrict__ nz) {
    size_t i = (size_t)blockIdx.x * blockDim.x + threadIdx.x;  // vec-of-4 index
    size_t total = (size_t)N * K / 4;
    if (i >= total) return;
    size_t base = i * 4;
    int o = (int)(base >> 12);       // / 4096  (K == 4096)
    int kk = (int)(base & 4095);
    int g = kk >> 7;                 // group of 128; 4 consecutive k share a group
    float s = __ldg(sc + (size_t)o * NGROUPS + g);
    float z = __ldg(zr + (size_t)o * NGROUPS + g);
    int4 qv = reinterpret_cast<const int4*>(q)[i];
    float4 nv = reinterpret_cast<const float4*>(nz)[i];
    float w0 = ((float)qv.x - z) * s; w0 = fmaf(ALPHA_C * nv.x, fabsf(w0), w0);
    float w1 = ((float)qv.y - z) * s; w1 = fmaf(ALPHA_C * nv.y, fabsf(w1), w1);
    float w2 = ((float)qv.z - z) * s; w2 = fmaf(ALPHA_C * nv.z, fabsf(w2), w2);
    float w3 = ((float)qv.w - z) * s; w3 = fmaf(ALPHA_C * nv.w, fabsf(w3), w3);
    __half2 h0 = __floats2half2_rn(w0, w1);
    __half2 h1 = __floats2half2_rn(w2, w3);
    uint2 u;
    u.x = *reinterpret_cast<u32*>(&h0);
    u.y = *reinterpret_cast<u32*>(&h1);
    reinterpret_cast<uint2*>(g_W)[i] = u;
}

__global__ void convert_x_kernel(const float* __restrict__ x) {
    size_t i = (size_t)blockIdx.x * blockDim.x + threadIdx.x;  // vec-of-4 index
    size_t total = (size_t)M * K / 4;
    if (i >= total) return;
    float4 v = reinterpret_cast<const float4*>(x)[i];
    __half2 h0 = __floats2half2_rn(v.x, v.y);
    __half2 h1 = __floats2half2_rn(v.z, v.w);
    uint2 u;
    u.x = *reinterpret_cast<u32*>(&h0);
    u.y = *reinterpret_cast<u32*>(&h1);
    reinterpret_cast<uint2*>(g_X)[i] = u;
}

// ---------------- GEMM kernel ----------------
// CTA: D[128,128] = Xh[128,K] @ Wh[128,K]^T + bias
// 8 warps (4 in M x 2 in N), warp tile 32x64, mma.sync m16n8k16.
// BK=64, 3 stages, 2 CTAs/SM (R8 winner). R12 adds zero-register software
// pipelining: in-place B-fragment rotation (ldsm for kstep+1 issues right
// after the mmas that consume each b-frag), A double-buffer (+8 regs), and
// the cp.async burst deferred until after kstep-0 fragments are in flight.

__device__ __forceinline__ void load_stage(u32 sb, int stage, int chunk, int tid,
                                           const __half* __restrict__ Ag,
                                           const __half* __restrict__ Bg) {
    int k0 = chunk * BK;
    u32 sA = sb + OFF_A + stage * A_BYTES;
    u32 sB = sb + OFF_B + stage * B_BYTES;
    // A: 128 rows x 128B = 1024 16B chunks; 256 threads -> 4 each
#pragma unroll
    for (int t = 0; t < 4; t++) {
        int s = tid + t * NTHREADS;
        int row = s >> 3, c = s & 7;
        cp16(sA + SWZ128(row * 128 + c * 16), Ag + (size_t)row * K + k0 + c * 8);
    }
#pragma unroll
    for (int t = 0; t < 4; t++) {
        int s = tid + t * NTHREADS;
        int row = s >> 3, c = s & 7;
        cp16(sB + SWZ128(row * 128 + c * 16), Bg + (size_t)row * K + k0 + c * 8);
    }
}

__global__ void __launch_bounds__(NTHREADS, 2)
gemm_f16_kernel(const float* __restrict__ bias, float* __restrict__ out) {
    extern __shared__ char smem[];
    u32 sb = smem_u32(smem);
    int tid = threadIdx.x;
    int wid = tid >> 5;
    int lid = tid & 31;
    int warpM = wid & 3;      // 0..3
    int warpN = wid >> 2;     // 0..1

    // raster swizzle: groups of RASTER_G n-blocks x all MBLKS m-blocks.
    // Keeps each wave's B working set (~8 MB) + A (~34 MB) inside L2.
    int id = blockIdx.x;
    int grp = id / (RASTER_G * MBLKS);
    int rem = id - grp * (RASTER_G * MBLKS);
    int gw = NBLKS - grp * RASTER_G;
    if (gw > RASTER_G) gw = RASTER_G;
    int mb = rem / gw;
    int nb = grp * RASTER_G + (rem - mb * gw);
    int m0 = mb * BM;
    int n0 = nb * BN;

    const __half* Ag = g_X + (size_t)m0 * K;
    const __half* Bg = g_W + (size_t)n0 * K;

    float acc[2][8][4];
#pragma unroll
    for (int mt = 0; mt < 2; mt++)
#pragma unroll
        for (int nt = 0; nt < 8; nt++)
#pragma unroll
            for (int c = 0; c < 4; c++) acc[mt][nt][c] = 0.0f;

    // ldmatrix lane geometry (x4: 4 8x8 tiles; lanes 0-15 rows, 16-31 k+8)
    int laneRow = (lid & 7) + ((lid >> 3) & 1) * 8;  // row within 16-row tile
    int laneHi = (lid >> 4) & 1;                     // +8 halves (1 chunk) in k

    int aRowBase = warpM * 32 + laneRow;             // + mt*16
    int bRowBase = warpN * 64 + laneRow;             // + nt16*16

    // prologue: stages 0..1 (chunks 0..1)
#pragma unroll
    for (int c = 0; c < STAGES - 1; c++) {
        load_stage(sb, c, c, tid, Ag, Bg);
        cp_commit();
    }

    int sComp = 0;           // stage holding chunk i
    int sLoad = STAGES - 1;  // stage receiving chunk i+2

    u32 afr[2][2][4];        // A fragments, double-buffered across ksteps
    u32 bf[4][4];            // B fragments, rotated in place

#pragma unroll 1
    for (int i = 0; i < NCHUNK; i++) {
        cp_wait<STAGES - 2>();   // chunk i resident (<=1 group pending)
        __syncthreads();         // all warps done with stage sLoad's old contents

        u32 sA = sb + OFF_A + sComp * A_BYTES;
        u32 sB = sb + OFF_B + sComp * B_BYTES;

        // kstep-0 fragments first, so the mma burst starts ASAP...
        {
            int chunkC = laneHi;
#pragma unroll
            for (int mt = 0; mt < 2; mt++) {
                u32 ad = sA + SWZ128((aRowBase + mt * 16) * 128 + chunkC * 16);
                ldsm_x4(afr[0][mt][0], afr[0][mt][1], afr[0][mt][2], afr[0][mt][3], ad);
            }
#pragma unroll
            for (int nt = 0; nt < 4; nt++) {
                u32 bd = sB + SWZ128((bRowBase + nt * 16) * 128 + chunkC * 16);
                ldsm_x4(bf[nt][0], bf[nt][1], bf[nt][2], bf[nt][3], bd);
            }
        }

        // ...then the 8-LDGSTS burst for chunk i+2 (its ~64 issue cycles
        // overlap the first mma burst instead of delaying it)
        int j = i + STAGES - 1;
        if (j < NCHUNK) load_stage(sb, sLoad, j, tid, Ag, Bg);
        cp_commit();             // exactly one group per iteration

#pragma unroll
        for (int ks = 0; ks < 4; ks++) {           // BK=64 -> 4 k16 steps
            int cur = ks & 1;
            int nxt = cur ^ 1;
            // A for next kstep up front (covered by the 16-mma burst below)
            if (ks < 3) {
                int chunkC = (ks + 1) * 2 + laneHi;
#pragma unroll
                for (int mt = 0; mt < 2; mt++) {
                    u32 ad = sA + SWZ128((aRowBase + mt * 16) * 128 + chunkC * 16);
                    ldsm_x4(afr[nxt][mt][0], afr[nxt][mt][1], afr[nxt][mt][2], afr[nxt][mt][3], ad);
                }
            }
#pragma unroll
            for (int nt = 0; nt < 4; nt++) {
                // consume bf[nt] (4 mmas), then immediately overwrite it
                // with kstep+1's data — forced ldsm/mma interleave, 0 extra regs
                mma16816(acc[0][nt * 2 + 0], afr[cur][0], bf[nt][0], bf[nt][2]);
                mma16816(acc[0][nt * 2 + 1], afr[cur][0], bf[nt][1], bf[nt][3]);
                mma16816(acc[1][nt * 2 + 0], afr[cur][1], bf[nt][0], bf[nt][2]);
                mma16816(acc[1][nt * 2 + 1], afr[cur][1], bf[nt][1], bf[nt][3]);
                if (ks < 3) {
                    int chunkC = (ks + 1) * 2 + laneHi;
                    u32 bd = sB + SWZ128((bRowBase + nt * 16) * 128 + chunkC * 16);
                    ldsm_x4(bf[nt][0], bf[nt][1], bf[nt][2], bf[nt][3], bd);
                }
            }
        }

        sComp = (sComp == STAGES - 1) ? 0 : sComp + 1;
        sLoad = (sLoad == STAGES - 1) ? 0 : sLoad + 1;
    }

    // epilogue: fragment layout m16n8: lane -> rows (l>>2, l>>2+8), cols (l&3)*2, +1
    int rBase = m0 + warpM * 32 + (lid >> 2);
    int cBase = n0 + warpN * 64 + (lid & 3) * 2;
#pragma unroll
    for (int mt = 0; mt < 2; mt++) {
#pragma unroll
        for (int nt = 0; nt < 8; nt++) {
            int col = cBase + nt * 8;
            float2 bz = *reinterpret_cast<const float2*>(bias + col);
            int r0 = rBase + mt * 16;
            float2 v0 = { acc[mt][nt][0] + bz.x, acc[mt][nt][1] + bz.y };
            float2 v1 = { acc[mt][nt][2] + bz.x, acc[mt][nt][3] + bz.y };
            *reinterpret_cast<float2*>(out + (size_t)r0 * N + col) = v0;
            *reinterpret_cast<float2*>(out + (size_t)(r0 + 8) * N + col) = v1;
        }
    }
}

// ---------------- launch ----------------
extern "C" void kernel_launch(void* const* d_in, const int* in_sizes, int n_in,
                              void* d_out, int out_size) {
    (void)in_sizes; (void)n_in; (void)out_size;
    const float* x    = (const float*)d_in[0];
    const int*   qw   = (const int*)d_in[1];
    const float* sc   = (const float*)d_in[2];
    const float* zr   = (const float*)d_in[3];
    const float* bias = (const float*)d_in[4];
    const float* nz   = (const float*)d_in[5];
    float* out = (float*)d_out;

    {
        size_t tot = (size_t)N * K / 4;   // 11,272,192
        dequant_noise_kernel<<<(unsigned)((tot + 255) / 256), 256>>>(qw, sc, zr, nz);
        size_t tx = (size_t)M * K / 4;    // 4,194,304
        convert_x_kernel<<<(unsigned)((tx + 255) / 256), 256>>>(x);
    }

    cudaFuncSetAttribute(gemm_f16_kernel,
                         cudaFuncAttributeMaxDynamicSharedMemorySize, SMEM_TOTAL);
    gemm_f16_kernel<<<MBLKS * NBLKS, NTHREADS, SMEM_TOTAL>>>(bias, out);
}

// round 15
// speedup vs baseline: 1.0711x; 1.0711x over previous
#include <cuda_runtime.h>
#include <cuda_fp16.h>

typedef unsigned int u32;
typedef unsigned long long u64;

// ---------------- problem constants ----------------
static constexpr int M = 4096;     // batch
static constexpr int N = 11008;    // out features
static constexpr int K = 4096;     // in features
static constexpr int NGROUPS = 32; // K / 128
static constexpr float ALPHA_C = 0.05f;

// ---------------- GEMM tiling (baseline-PTX Ampere-style) ----------------
static constexpr int BM = 128;
static constexpr int BN = 128;
static constexpr int BK = 64;                // halves per chunk (128B rows, SW128)
static constexpr int STAGES = 3;
static constexpr int NCHUNK = K / BK;        // 64
static constexpr int NTHREADS = 256;         // 8 warps, each 32x64

static constexpr int A_BYTES = BM * BK * 2;  // 16384
static constexpr int B_BYTES = BN * BK * 2;  // 16384
static constexpr int OFF_A = 0;
static constexpr int OFF_B = STAGES * A_BYTES;               // 49152
static constexpr int SMEM_TOTAL = OFF_B + STAGES * B_BYTES;  // 98304 (96KB, 2 CTAs/SM)

static constexpr int MBLKS = M / BM;         // 32
static constexpr int NBLKS = N / BN;         // 86
static constexpr int RASTER_G = 16;          // n-blocks per raster group (6 groups)

// ---------------- scratch (no cudaMalloc allowed) ----------------
__device__ __half g_W[(size_t)N * K];   // dequantized noisy weights, fp16, [N,K] row-major
__device__ __half g_X[(size_t)M * K];   // x in fp16, [M,K] row-major

// ---------------- helpers ----------------
__device__ __forceinline__ u32 smem_u32(const void* p) {
    u32 a;
    asm("{ .reg .u64 t; cvta.to.shared.u64 t, %1; cvt.u32.u64 %0, t; }" : "=r"(a) : "l"(p));
    return a;
}
__device__ __forceinline__ void cp16(u32 dst, const void* src) {
    asm volatile("cp.async.cg.shared.global [%0], [%1], 16;" :: "r"(dst), "l"(src));
}
__device__ __forceinline__ void cp_commit() { asm volatile("cp.async.commit_group;"); }
template <int NN> __device__ __forceinline__ void cp_wait() {
    asm volatile("cp.async.wait_group %0;" :: "n"(NN));
}
__device__ __forceinline__ void ldsm_x4(u32& r0, u32& r1, u32& r2, u32& r3, u32 addr) {
    asm volatile("ldmatrix.sync.aligned.m8n8.x4.shared.b16 {%0,%1,%2,%3}, [%4];"
                 : "=r"(r0), "=r"(r1), "=r"(r2), "=r"(r3) : "r"(addr));
}
__device__ __forceinline__ void mma16816(float* d, const u32* a, u32 b0, u32 b1) {
    asm volatile(
        "mma.sync.aligned.m16n8k16.row.col.f32.f16.f16.f32 "
        "{%0,%1,%2,%3}, {%4,%5,%6,%7}, {%8,%9}, {%0,%1,%2,%3};"
        : "+f"(d[0]), "+f"(d[1]), "+f"(d[2]), "+f"(d[3])
        : "r"(a[0]), "r"(a[1]), "r"(a[2]), "r"(a[3]), "r"(b0), "r"(b1));
}

// SW128 swizzle for 128B rows: bits[6:4] ^= bits[9:7]
#define SWZ128(o) ((u32)(o) ^ ((((u32)(o)) >> 3) & 0x70))

// ---------------- prep kernels ----------------
// W_noisy[o,k] = fp16( w + 0.05*noise*|w| ),  w = (q - zero[o,g]) * scale[o,g]
__global__ void dequant_noise_kernel(const int* __restrict__ q,
                                     const float* __restrict__ sc,
                                     const float* __restrict__ zr,
                                     const float* __restrict__ nz) {
    size_t i = (size_t)blockIdx.x * blockDim.x + threadIdx.x;  // vec-of-4 index
    size_t total = (size_t)N * K / 4;
    if (i >= total) return;
    size_t base = i * 4;
    int o = (int)(base >> 12);       // / 4096  (K == 4096)
    int kk = (int)(base & 4095);
    int g = kk >> 7;                 // group of 128; 4 consecutive k share a group
    float s = __ldg(sc + (size_t)o * NGROUPS + g);
    float z = __ldg(zr + (size_t)o * NGROUPS + g);
    int4 qv = reinterpret_cast<const int4*>(q)[i];
    float4 nv = reinterpret_cast<const float4*>(nz)[i];
    float w0 = ((float)qv.x - z) * s; w0 = fmaf(ALPHA_C * nv.x, fabsf(w0), w0);
    float w1 = ((float)qv.y - z) * s; w1 = fmaf(ALPHA_C * nv.y, fabsf(w1), w1);
    float w2 = ((float)qv.z - z) * s; w2 = fmaf(ALPHA_C * nv.z, fabsf(w2), w2);
    float w3 = ((float)qv.w - z) * s; w3 = fmaf(ALPHA_C * nv.w, fabsf(w3), w3);
    __half2 h0 = __floats2half2_rn(w0, w1);
    __half2 h1 = __floats2half2_rn(w2, w3);
    uint2 u;
    u.x = *reinterpret_cast<u32*>(&h0);
    u.y = *reinterpret_cast<u32*>(&h1);
    reinterpret_cast<uint2*>(g_W)[i] = u;
}

__global__ void convert_x_kernel(const float* __restrict__ x) {
    size_t i = (size_t)blockIdx.x * blockDim.x + threadIdx.x;  // vec-of-4 index
    size_t total = (size_t)M * K / 4;
    if (i >= total) return;
    float4 v = reinterpret_cast<const float4*>(x)[i];
    __half2 h0 = __floats2half2_rn(v.x, v.y);
    __half2 h1 = __floats2half2_rn(v.z, v.w);
    uint2 u;
    u.x = *reinterpret_cast<u32*>(&h0);
    u.y = *reinterpret_cast<u32*>(&h1);
    reinterpret_cast<uint2*>(g_X)[i] = u;
}

// ---------------- GEMM kernel ----------------
// CTA: D[128,128] = Xh[128,K] @ Wh[128,K]^T + bias
// 8 warps (4 in M x 2 in N), warp tile 32x64, mma.sync m16n8k16.
// BK=64, 3 stages, 2 CTAs/SM (R8 winner, body untouched).
// RASTER_G=16: 6 raster groups -> A re-read from DRAM 6x instead of 11x;
// group working set (34MB A + 16MB B) still L2-resident.

__device__ __forceinline__ void load_stage(u32 sb, int stage, int chunk, int tid,
                                           const __half* __restrict__ Ag,
                                           const __half* __restrict__ Bg) {
    int k0 = chunk * BK;
    u32 sA = sb + OFF_A + stage * A_BYTES;
    u32 sB = sb + OFF_B + stage * B_BYTES;
    // A: 128 rows x 128B = 1024 16B chunks; 256 threads -> 4 each
#pragma unroll
    for (int t = 0; t < 4; t++) {
        int s = tid + t * NTHREADS;
        int row = s >> 3, c = s & 7;
        cp16(sA + SWZ128(row * 128 + c * 16), Ag + (size_t)row * K + k0 + c * 8);
    }
#pragma unroll
    for (int t = 0; t < 4; t++) {
        int s = tid + t * NTHREADS;
        int row = s >> 3, c = s & 7;
        cp16(sB + SWZ128(row * 128 + c * 16), Bg + (size_t)row * K + k0 + c * 8);
    }
}

__global__ void __launch_bounds__(NTHREADS, 2)
gemm_f16_kernel(const float* __restrict__ bias, float* __restrict__ out) {
    extern __shared__ char smem[];
    u32 sb = smem_u32(smem);
    int tid = threadIdx.x;
    int wid = tid >> 5;
    int lid = tid & 31;
    int warpM = wid & 3;      // 0..3
    int warpN = wid >> 2;     // 0..1

    // raster swizzle: groups of RASTER_G n-blocks x all MBLKS m-blocks.
    int id = blockIdx.x;
    int grp = id / (RASTER_G * MBLKS);
    int rem = id - grp * (RASTER_G * MBLKS);
    int gw = NBLKS - grp * RASTER_G;
    if (gw > RASTER_G) gw = RASTER_G;
    int mb = rem / gw;
    int nb = grp * RASTER_G + (rem - mb * gw);
    int m0 = mb * BM;
    int n0 = nb * BN;

    const __half* Ag = g_X + (size_t)m0 * K;
    const __half* Bg = g_W + (size_t)n0 * K;

    float acc[2][8][4];
#pragma unroll
    for (int mt = 0; mt < 2; mt++)
#pragma unroll
        for (int nt = 0; nt < 8; nt++)
#pragma unroll
            for (int c = 0; c < 4; c++) acc[mt][nt][c] = 0.0f;

    // ldmatrix lane geometry (x4: 4 8x8 tiles; lanes 0-15 rows, 16-31 k+8)
    int laneRow = (lid & 7) + ((lid >> 3) & 1) * 8;  // row within 16-row tile
    int laneHi = (lid >> 4) & 1;                     // +8 halves (1 chunk) in k

    int aRowBase = warpM * 32 + laneRow;             // + mt*16
    int bRowBase = warpN * 64 + laneRow;             // + nt16*16

    // prologue: stages 0..1 (chunks 0..1)
#pragma unroll
    for (int c = 0; c < STAGES - 1; c++) {
        load_stage(sb, c, c, tid, Ag, Bg);
        cp_commit();
    }

    int sComp = 0;           // stage holding chunk i
    int sLoad = STAGES - 1;  // stage receiving chunk i+2

#pragma unroll 1
    for (int i = 0; i < NCHUNK; i++) {
        cp_wait<STAGES - 2>();   // chunk i resident (<=1 group pending)
        __syncthreads();         // all warps done with stage sLoad's old contents

        int j = i + STAGES - 1;
        if (j < NCHUNK) load_stage(sb, sLoad, j, tid, Ag, Bg);
        cp_commit();             // exactly one group per iteration

        u32 sA = sb + OFF_A + sComp * A_BYTES;
        u32 sB = sb + OFF_B + sComp * B_BYTES;

#pragma unroll
        for (int ks = 0; ks < 4; ks++) {           // BK=64 -> 4 k16 steps
            int chunkC = ks * 2 + laneHi;          // 16B chunk within 128B row
            u32 a[2][4];
#pragma unroll
            for (int mt = 0; mt < 2; mt++) {
                u32 ad = sA + SWZ128((aRowBase + mt * 16) * 128 + chunkC * 16);
                ldsm_x4(a[mt][0], a[mt][1], a[mt][2], a[mt][3], ad);
            }
            u32 bf[4][4];
#pragma unroll
            for (int nt = 0; nt < 4; nt++) {       // 4 x n16 tiles = 64 cols
                u32 bd = sB + SWZ128((bRowBase + nt * 16) * 128 + chunkC * 16);
                ldsm_x4(bf[nt][0], bf[nt][1], bf[nt][2], bf[nt][3], bd);
            }
#pragma unroll
            for (int mt = 0; mt < 2; mt++)
#pragma unroll
                for (int nt = 0; nt < 4; nt++) {
                    // n16 tile -> two n8 frags: even {r0,r2}, odd {r1,r3}
                    mma16816(acc[mt][nt * 2 + 0], a[mt], bf[nt][0], bf[nt][2]);
                    mma16816(acc[mt][nt * 2 + 1], a[mt], bf[nt][1], bf[nt][3]);
                }
        }

        sComp = (sComp == STAGES - 1) ? 0 : sComp + 1;
        sLoad = (sLoad == STAGES - 1) ? 0 : sLoad + 1;
    }

    // epilogue: fragment layout m16n8: lane -> rows (l>>2, l>>2+8), cols (l&3)*2, +1
    int rBase = m0 + warpM * 32 + (lid >> 2);
    int cBase = n0 + warpN * 64 + (lid & 3) * 2;
#pragma unroll
    for (int mt = 0; mt < 2; mt++) {
#pragma unroll
        for (int nt = 0; nt < 8; nt++) {
            int col = cBase + nt * 8;
            float2 bz = *reinterpret_cast<const float2*>(bias + col);
            int r0 = rBase + mt * 16;
            float2 v0 = { acc[mt][nt][0] + bz.x, acc[mt][nt][1] + bz.y };
            float2 v1 = { acc[mt][nt][2] + bz.x, acc[mt][nt][3] + bz.y };
            *reinterpret_cast<float2*>(out + (size_t)r0 * N + col) = v0;
            *reinterpret_cast<float2*>(out + (size_t)(r0 + 8) * N + col) = v1;
        }
    }
}

// ---------------- launch ----------------
extern "C" void kernel_launch(void* const* d_in, const int* in_sizes, int n_in,
                              void* d_out, int out_size) {
    (void)in_sizes; (void)n_in; (void)out_size;
    const float* x    = (const float*)d_in[0];
    const int*   qw   = (const int*)d_in[1];
    const float* sc   = (const float*)d_in[2];
    const float* zr   = (const float*)d_in[3];
    const float* bias = (const float*)d_in[4];
    const float* nz   = (const float*)d_in[5];
    float* out = (float*)d_out;

    {
        size_t tot = (size_t)N * K / 4;   // 11,272,192
        dequant_noise_kernel<<<(unsigned)((tot + 255) / 256), 256>>>(qw, sc, zr, nz);
        size_t tx = (size_t)M * K / 4;    // 4,194,304
        convert_x_kernel<<<(unsigned)((tx + 255) / 256), 256>>>(x);
    }

    cudaFuncSetAttribute(gemm_f16_kernel,
                         cudaFuncAttributeMaxDynamicSharedMemorySize, SMEM_TOTAL);
    gemm_f16_kernel<<<MBLKS * NBLKS, NTHREADS, SMEM_TOTAL>>>(bias, out);
}